// round 6
// baseline (speedup 1.0000x reference)
#include <cuda_runtime.h>
#include <math.h>

#define T_LEN  1024
#define D_DIM  256
#define K_CH   4
#define NCHUNK 128
#define L_CH   8          // T_LEN / NCHUNK
#define NROUND 7          // log2(NCHUNK)

// Constants passed by value (computed in double on host; deterministic).
struct HippoConsts {
    float Ab[16];              // Abar (row-major 4x4)
    float Bb[4];               // Bbar
    float Pk[NROUND][16];      // Abar^(L_CH * 2^r), r = 0..6
};

// Static scratch (no allocs). B <= 8 supported.
__device__ float4 g_start[8 * NCHUNK * D_DIM];  // start-states, [b][j][d]

// One recurrence step: x = Ab*x + Bb*hv
#define RSTEP(hv)                                                              \
    {                                                                          \
        float y0 = fmaf(c.Ab[0],  x0, fmaf(c.Ab[1],  x1,                       \
                   fmaf(c.Ab[2],  x2, fmaf(c.Ab[3],  x3, c.Bb[0] * (hv)))));   \
        float y1 = fmaf(c.Ab[4],  x0, fmaf(c.Ab[5],  x1,                       \
                   fmaf(c.Ab[6],  x2, fmaf(c.Ab[7],  x3, c.Bb[1] * (hv)))));   \
        float y2 = fmaf(c.Ab[8],  x0, fmaf(c.Ab[9],  x1,                       \
                   fmaf(c.Ab[10], x2, fmaf(c.Ab[11], x3, c.Bb[2] * (hv)))));   \
        float y3 = fmaf(c.Ab[12], x0, fmaf(c.Ab[13], x1,                       \
                   fmaf(c.Ab[14], x2, fmaf(c.Ab[15], x3, c.Bb[3] * (hv)))));   \
        x0 = y0; x1 = y1; x2 = y2; x3 = y3;                                    \
    }

// v = M*p + v  (4x4 matvec-accumulate on float4)
__device__ __forceinline__ float4 mvacc(const float* M, float4 p, float4 v) {
    float4 r;
    r.x = fmaf(M[0],  p.x, fmaf(M[1],  p.y, fmaf(M[2],  p.z, fmaf(M[3],  p.w, v.x))));
    r.y = fmaf(M[4],  p.x, fmaf(M[5],  p.y, fmaf(M[6],  p.z, fmaf(M[7],  p.w, v.y))));
    r.z = fmaf(M[8],  p.x, fmaf(M[9],  p.y, fmaf(M[10], p.z, fmaf(M[11], p.w, v.z))));
    r.w = fmaf(M[12], p.x, fmaf(M[13], p.y, fmaf(M[14], p.z, fmaf(M[15], p.w, v.w))));
    return r;
}

// swizzled column index: p(t) = t + t/8  (stride-9 per chunk -> conflict-free LDS)
#define SWZ(t) ((t) + ((t) >> 3))
#define COLP   (T_LEN + (T_LEN >> 3))   // 1152 floats per dd-plane

// ---- KS': per (b, d-pair): compute chunk end-states from h, scan, write starts ----
// Block: 256 threads = 128 chunks (j) x 2 d-values (dd). grid (D_DIM/2, B).
__global__ __launch_bounds__(256)
void hippo_ks1(const float* __restrict__ h, HippoConsts c) {
    __shared__ float sh[2 * COLP];   // column pair, swizzled: sh[dd*COLP + SWZ(t)]
    __shared__ float4 s[256];        // scan workspace

    const int tid = threadIdx.x;
    const int d0  = blockIdx.x * 2;
    const int b   = blockIdx.y;

    // load the (d0, d0+1) column of h: thread tid covers t = tid + r*256
    #pragma unroll
    for (int r = 0; r < 4; r++) {
        const int t = tid + r * 256;
        float2 v = __ldg((const float2*)(h + ((size_t)(b * T_LEN + t)) * D_DIM + d0));
        const int p = SWZ(t);
        sh[p]        = v.x;
        sh[COLP + p] = v.y;
    }
    __syncthreads();

    // chunk-local recurrence: thread (j, dd) runs 8 steps for its column
    const int j  = tid & (NCHUNK - 1);
    const int dd = tid >> 7;
    const float* col = sh + dd * COLP + j * (L_CH + 1);   // SWZ(j*8) = j*9

    float x0 = 0.f, x1 = 0.f, x2 = 0.f, x3 = 0.f;
    #pragma unroll
    for (int t = 0; t < L_CH; t++) {
        float hv = col[t];
        RSTEP(hv);
    }
    float4 v = make_float4(x0, x1, x2, x3);
    s[tid] = v;
    __syncthreads();

    // Kogge-Stone affine scan over 128 chunks
    #pragma unroll
    for (int r = 0; r < NROUND; r++) {
        const int off = 1 << r;
        float4 prev = make_float4(0.f, 0.f, 0.f, 0.f);
        const bool pred = (j >= off);
        if (pred) prev = s[tid - off];
        __syncthreads();
        if (pred) v = mvacc(c.Pk[r], prev, v);   // v += P^(2^r) * prev
        s[tid] = v;
        __syncthreads();
    }

    // exclusive prefix -> start states, [b][j][d] layout (coalesced reads in K2)
    float4 st = make_float4(0.f, 0.f, 0.f, 0.f);
    if (j > 0) st = s[tid - 1];
    g_start[((size_t)b * NCHUNK + j) * D_DIM + d0 + dd] = st;
}

// ---- K2: replay each chunk from its start state, writing all outputs ----
__global__ __launch_bounds__(D_DIM)
void hippo_k2(const float* __restrict__ h, float* __restrict__ out, HippoConsts c) {
    __shared__ float sh[L_CH * D_DIM];   // 8KB chunk stage
    const int tid = threadIdx.x;
    const int j = blockIdx.x;
    const int b = blockIdx.y;

    // issue start-state + h loads together (independent)
    float4 xs = g_start[((size_t)b * NCHUNK + j) * D_DIM + tid];
    const float4* src = (const float4*)(h + ((size_t)(b * T_LEN + j * L_CH)) * D_DIM);
    float4 v0 = __ldg(src + tid);
    float4 v1 = __ldg(src + D_DIM + tid);
    ((float4*)sh)[tid] = v0;
    ((float4*)sh)[D_DIM + tid] = v1;
    __syncthreads();

    float x0 = xs.x, x1 = xs.y, x2 = xs.z, x3 = xs.w;
    float* op = out + ((size_t)(b * T_LEN + j * L_CH)) * K_CH * D_DIM + tid;

    #pragma unroll
    for (int t = 0; t < L_CH; t++) {
        float hv = sh[t * D_DIM + tid];
        RSTEP(hv);
        op[0]         = x0;
        op[D_DIM]     = x1;
        op[2 * D_DIM] = x2;
        op[3 * D_DIM] = x3;
        op += (size_t)K_CH * D_DIM;
    }
}

// ---------------- host-side constant construction (double precision) ----------------

static void inv4x4(const double Min[4][4], double Mout[4][4]) {
    double a[4][8];
    for (int i = 0; i < 4; i++)
        for (int jj = 0; jj < 8; jj++)
            a[i][jj] = (jj < 4) ? Min[i][jj] : (jj - 4 == i ? 1.0 : 0.0);
    for (int col = 0; col < 4; col++) {
        int p = col;
        for (int rr = col + 1; rr < 4; rr++)
            if (fabs(a[rr][col]) > fabs(a[p][col])) p = rr;
        if (p != col)
            for (int jj = 0; jj < 8; jj++) { double t = a[col][jj]; a[col][jj] = a[p][jj]; a[p][jj] = t; }
        double piv = a[col][col];
        for (int jj = 0; jj < 8; jj++) a[col][jj] /= piv;
        for (int rr = 0; rr < 4; rr++) {
            if (rr == col) continue;
            double f = a[rr][col];
            for (int jj = 0; jj < 8; jj++) a[rr][jj] -= f * a[col][jj];
        }
    }
    for (int i = 0; i < 4; i++)
        for (int jj = 0; jj < 4; jj++)
            Mout[i][jj] = a[i][jj + 4];
}

static void matmul4(const double A[4][4], const double B[4][4], double C[4][4]) {
    for (int i = 0; i < 4; i++)
        for (int jj = 0; jj < 4; jj++) {
            double s = 0.0;
            for (int k = 0; k < 4; k++) s += A[i][k] * B[k][jj];
            C[i][jj] = s;
        }
}

extern "C" void kernel_launch(void* const* d_in, const int* in_sizes, int n_in,
                              void* d_out, int out_size) {
    const float* h;
    int sz0 = in_sizes[0], sz1 = in_sizes[1];
    if (sz0 > sz1) h = (const float*)d_in[0];
    else           h = (const float*)d_in[1];
    int hsz = (sz0 > sz1) ? sz0 : sz1;
    int B = hsz / (T_LEN * D_DIM);

    // --- HiPPO-LegT constants (matches reference _make_hippo_legt + bilinear) ---
    const double theta = 200.0;
    const double dt = 1.0 / theta;
    double A[4][4], Bv[4], Pn[4];
    for (int i = 0; i < 4; i++) Pn[i] = sqrt(2.0 * i + 1.0);
    for (int i = 0; i < 4; i++) {
        Bv[i] = Pn[i];
        for (int jj = 0; jj < 4; jj++) {
            double sg = 1.0;
            if (jj > i && ((jj - i) & 1)) sg = -1.0;   // (-1)^(j-i) upper triangle
            A[i][jj] = -Pn[i] * Pn[jj] * sg;
        }
    }
    double ImA[4][4], IpA[4][4], Inv[4][4], Abar[4][4];
    for (int i = 0; i < 4; i++)
        for (int jj = 0; jj < 4; jj++) {
            double eye = (i == jj) ? 1.0 : 0.0;
            ImA[i][jj] = eye - 0.5 * dt * A[i][jj];
            IpA[i][jj] = eye + 0.5 * dt * A[i][jj];
        }
    inv4x4(ImA, Inv);
    matmul4(Inv, IpA, Abar);
    double Bbar[4];
    for (int i = 0; i < 4; i++) {
        double sacc = 0.0;
        for (int jj = 0; jj < 4; jj++) sacc += Inv[i][jj] * Bv[jj] * dt;
        Bbar[i] = sacc;
    }

    // Pk[r] = Abar^(L_CH * 2^r)
    double Pw[NROUND][4][4], Tmp[4][4], Cur[4][4];
    for (int i = 0; i < 4; i++)
        for (int jj = 0; jj < 4; jj++) Cur[i][jj] = (i == jj) ? 1.0 : 0.0;
    for (int m = 0; m < L_CH; m++) {
        matmul4(Cur, Abar, Tmp);
        for (int i = 0; i < 4; i++)
            for (int jj = 0; jj < 4; jj++) Cur[i][jj] = Tmp[i][jj];
    }
    for (int i = 0; i < 4; i++)
        for (int jj = 0; jj < 4; jj++) Pw[0][i][jj] = Cur[i][jj];
    for (int r = 1; r < NROUND; r++) {
        matmul4(Pw[r - 1], Pw[r - 1], Tmp);
        for (int i = 0; i < 4; i++)
            for (int jj = 0; jj < 4; jj++) Pw[r][i][jj] = Tmp[i][jj];
    }

    HippoConsts c;
    for (int i = 0; i < 4; i++) {
        c.Bb[i] = (float)Bbar[i];
        for (int jj = 0; jj < 4; jj++)
            c.Ab[i * 4 + jj] = (float)Abar[i][jj];
    }
    for (int r = 0; r < NROUND; r++)
        for (int i = 0; i < 16; i++)
            c.Pk[r][i] = (float)Pw[r][i / 4][i % 4];

    dim3 gridS(D_DIM / 2, B);       // 128 x B
    dim3 gridC(NCHUNK, B);          // 128 x B
    hippo_ks1<<<gridS, 256>>>(h, c);
    hippo_k2<<<gridC, D_DIM>>>(h, (float*)d_out, c);
}

// round 7
// speedup vs baseline: 1.0208x; 1.0208x over previous
#include <cuda_runtime.h>
#include <math.h>

#define T_LEN  1024
#define D_DIM  256
#define K_CH   4
#define L_CH   16        // timesteps per chunk
#define NCHUNK 64        // T_LEN / L_CH
#define NROUND 6         // log2(NCHUNK)
#define DG     8         // d-columns per block
#define NTHR   (NCHUNK * DG)   // 512 threads

// Constants passed by value (computed in double on host; deterministic).
struct HippoConsts {
    float Ab[16];              // Abar (row-major 4x4)
    float Bb[4];               // Bbar
    float Pk[NROUND][16];      // Abar^(L_CH * 2^r), r = 0..NROUND-1
};

// One recurrence step: x = Ab*x + Bb*hv
#define RSTEP(hv)                                                              \
    {                                                                          \
        float y0 = fmaf(c.Ab[0],  x0, fmaf(c.Ab[1],  x1,                       \
                   fmaf(c.Ab[2],  x2, fmaf(c.Ab[3],  x3, c.Bb[0] * (hv)))));   \
        float y1 = fmaf(c.Ab[4],  x0, fmaf(c.Ab[5],  x1,                       \
                   fmaf(c.Ab[6],  x2, fmaf(c.Ab[7],  x3, c.Bb[1] * (hv)))));   \
        float y2 = fmaf(c.Ab[8],  x0, fmaf(c.Ab[9],  x1,                       \
                   fmaf(c.Ab[10], x2, fmaf(c.Ab[11], x3, c.Bb[2] * (hv)))));   \
        float y3 = fmaf(c.Ab[12], x0, fmaf(c.Ab[13], x1,                       \
                   fmaf(c.Ab[14], x2, fmaf(c.Ab[15], x3, c.Bb[3] * (hv)))));   \
        x0 = y0; x1 = y1; x2 = y2; x3 = y3;                                    \
    }

// v = M*p + v  (4x4 matvec-accumulate on float4)
__device__ __forceinline__ float4 mvacc(const float* M, float4 p, float4 v) {
    float4 r;
    r.x = fmaf(M[0],  p.x, fmaf(M[1],  p.y, fmaf(M[2],  p.z, fmaf(M[3],  p.w, v.x))));
    r.y = fmaf(M[4],  p.x, fmaf(M[5],  p.y, fmaf(M[6],  p.z, fmaf(M[7],  p.w, v.y))));
    r.z = fmaf(M[8],  p.x, fmaf(M[9],  p.y, fmaf(M[10], p.z, fmaf(M[11], p.w, v.z))));
    r.w = fmaf(M[12], p.x, fmaf(M[13], p.y, fmaf(M[14], p.z, fmaf(M[15], p.w, v.w))));
    return r;
}

// Single kernel: block = (b, group of 8 d-columns). No cross-block deps.
// Threads: tid = j*8 + dd  (j = chunk 0..63, dd = d within group 0..7).
__global__ __launch_bounds__(NTHR)
void hippo_one(const float* __restrict__ h, float* __restrict__ out, HippoConsts c) {
    __shared__ float  sh[T_LEN * (DG + 1)];   // slab: sh[t*9 + dd], stride-9 padding
    __shared__ float4 s[NTHR];                // scan workspace

    const int tid = threadIdx.x;
    const int g   = blockIdx.x;               // d-group index (0..31)
    const int b   = blockIdx.y;
    const int d0  = g * DG;

    // ---- stage the 8-column slab: thread handles rows tid and tid+512 ----
    {
        const float* hb = h + (size_t)b * T_LEN * D_DIM + d0;
        #pragma unroll
        for (int r = 0; r < T_LEN / NTHR; r++) {
            const int row = tid + r * NTHR;
            float4 a0 = __ldg((const float4*)(hb + (size_t)row * D_DIM));
            float4 a1 = __ldg((const float4*)(hb + (size_t)row * D_DIM + 4));
            float* dst = sh + row * (DG + 1);
            dst[0] = a0.x; dst[1] = a0.y; dst[2] = a0.z; dst[3] = a0.w;
            dst[4] = a1.x; dst[5] = a1.y; dst[6] = a1.z; dst[7] = a1.w;
        }
    }
    __syncthreads();

    const int j  = tid >> 3;          // chunk
    const int dd = tid & 7;           // d within group
    const float* col = sh + (size_t)(j * L_CH) * (DG + 1) + dd;

    // ---- chunk-local recurrence (zero init) ----
    float x0 = 0.f, x1 = 0.f, x2 = 0.f, x3 = 0.f;
    #pragma unroll
    for (int t = 0; t < L_CH; t++) {
        float hv = col[t * (DG + 1)];
        RSTEP(hv);
    }
    float4 v = make_float4(x0, x1, x2, x3);
    s[tid] = v;
    __syncthreads();

    // ---- Kogge-Stone affine scan over 64 chunks (per dd independently) ----
    #pragma unroll
    for (int r = 0; r < NROUND; r++) {
        const int off = 1 << r;
        float4 prev = make_float4(0.f, 0.f, 0.f, 0.f);
        const bool pred = (j >= off);
        if (pred) prev = s[tid - off * DG];
        __syncthreads();
        if (pred) v = mvacc(c.Pk[r], prev, v);   // v += P^(2^r) * prev
        s[tid] = v;
        __syncthreads();
    }

    // exclusive prefix = this chunk's start state
    float4 st = make_float4(0.f, 0.f, 0.f, 0.f);
    if (j > 0) st = s[tid - DG];

    // ---- replay chunk from start state, write outputs ----
    x0 = st.x; x1 = st.y; x2 = st.z; x3 = st.w;
    float* op = out + (((size_t)b * T_LEN + j * L_CH) * K_CH) * D_DIM + d0 + dd;

    #pragma unroll
    for (int t = 0; t < L_CH; t++) {
        float hv = col[t * (DG + 1)];
        RSTEP(hv);
        op[0]         = x0;
        op[D_DIM]     = x1;
        op[2 * D_DIM] = x2;
        op[3 * D_DIM] = x3;
        op += (size_t)K_CH * D_DIM;
    }
}

// ---------------- host-side constant construction (double precision) ----------------

static void inv4x4(const double Min[4][4], double Mout[4][4]) {
    double a[4][8];
    for (int i = 0; i < 4; i++)
        for (int jj = 0; jj < 8; jj++)
            a[i][jj] = (jj < 4) ? Min[i][jj] : (jj - 4 == i ? 1.0 : 0.0);
    for (int col = 0; col < 4; col++) {
        int p = col;
        for (int rr = col + 1; rr < 4; rr++)
            if (fabs(a[rr][col]) > fabs(a[p][col])) p = rr;
        if (p != col)
            for (int jj = 0; jj < 8; jj++) { double t = a[col][jj]; a[col][jj] = a[p][jj]; a[p][jj] = t; }
        double piv = a[col][col];
        for (int jj = 0; jj < 8; jj++) a[col][jj] /= piv;
        for (int rr = 0; rr < 4; rr++) {
            if (rr == col) continue;
            double f = a[rr][col];
            for (int jj = 0; jj < 8; jj++) a[rr][jj] -= f * a[col][jj];
        }
    }
    for (int i = 0; i < 4; i++)
        for (int jj = 0; jj < 4; jj++)
            Mout[i][jj] = a[i][jj + 4];
}

static void matmul4(const double A[4][4], const double B[4][4], double C[4][4]) {
    for (int i = 0; i < 4; i++)
        for (int jj = 0; jj < 4; jj++) {
            double s = 0.0;
            for (int k = 0; k < 4; k++) s += A[i][k] * B[k][jj];
            C[i][jj] = s;
        }
}

extern "C" void kernel_launch(void* const* d_in, const int* in_sizes, int n_in,
                              void* d_out, int out_size) {
    const float* h;
    int sz0 = in_sizes[0], sz1 = in_sizes[1];
    if (sz0 > sz1) h = (const float*)d_in[0];
    else           h = (const float*)d_in[1];
    int hsz = (sz0 > sz1) ? sz0 : sz1;
    int B = hsz / (T_LEN * D_DIM);

    // --- HiPPO-LegT constants (matches reference _make_hippo_legt + bilinear) ---
    const double theta = 200.0;
    const double dt = 1.0 / theta;
    double A[4][4], Bv[4], Pn[4];
    for (int i = 0; i < 4; i++) Pn[i] = sqrt(2.0 * i + 1.0);
    for (int i = 0; i < 4; i++) {
        Bv[i] = Pn[i];
        for (int jj = 0; jj < 4; jj++) {
            double sg = 1.0;
            if (jj > i && ((jj - i) & 1)) sg = -1.0;   // (-1)^(j-i) upper triangle
            A[i][jj] = -Pn[i] * Pn[jj] * sg;
        }
    }
    double ImA[4][4], IpA[4][4], Inv[4][4], Abar[4][4];
    for (int i = 0; i < 4; i++)
        for (int jj = 0; jj < 4; jj++) {
            double eye = (i == jj) ? 1.0 : 0.0;
            ImA[i][jj] = eye - 0.5 * dt * A[i][jj];
            IpA[i][jj] = eye + 0.5 * dt * A[i][jj];
        }
    inv4x4(ImA, Inv);
    matmul4(Inv, IpA, Abar);
    double Bbar[4];
    for (int i = 0; i < 4; i++) {
        double sacc = 0.0;
        for (int jj = 0; jj < 4; jj++) sacc += Inv[i][jj] * Bv[jj] * dt;
        Bbar[i] = sacc;
    }

    // Pk[r] = Abar^(L_CH * 2^r): Pk[0] = Abar^16, Pk[r] = Pk[r-1]^2
    double Pw[NROUND][4][4], Tmp[4][4], Cur[4][4];
    for (int i = 0; i < 4; i++)
        for (int jj = 0; jj < 4; jj++) Cur[i][jj] = (i == jj) ? 1.0 : 0.0;
    for (int m = 0; m < L_CH; m++) {
        matmul4(Cur, Abar, Tmp);
        for (int i = 0; i < 4; i++)
            for (int jj = 0; jj < 4; jj++) Cur[i][jj] = Tmp[i][jj];
    }
    for (int i = 0; i < 4; i++)
        for (int jj = 0; jj < 4; jj++) Pw[0][i][jj] = Cur[i][jj];
    for (int r = 1; r < NROUND; r++) {
        matmul4(Pw[r - 1], Pw[r - 1], Tmp);
        for (int i = 0; i < 4; i++)
            for (int jj = 0; jj < 4; jj++) Pw[r][i][jj] = Tmp[i][jj];
    }

    HippoConsts c;
    for (int i = 0; i < 4; i++) {
        c.Bb[i] = (float)Bbar[i];
        for (int jj = 0; jj < 4; jj++)
            c.Ab[i * 4 + jj] = (float)Abar[i][jj];
    }
    for (int r = 0; r < NROUND; r++)
        for (int i = 0; i < 16; i++)
            c.Pk[r][i] = (float)Pw[r][i / 4][i % 4];

    dim3 grid(D_DIM / DG, B);   // 32 x B blocks, fully independent
    hippo_one<<<grid, NTHR>>>(h, (float*)d_out, c);
}

// round 8
// speedup vs baseline: 1.0239x; 1.0030x over previous
#include <cuda_runtime.h>
#include <math.h>

#define T_LEN  1024
#define D_DIM  256
#define K_CH   4
#define NCHUNK 128
#define L_CH   8          // T_LEN / NCHUNK
#define NROUND 7          // log2(NCHUNK)
#define DG     4          // d-columns per scan block
#define ATHR   (NCHUNK * DG)   // 512 threads in kernel A

// Constants passed by value (computed in double on host; deterministic).
struct HippoConsts {
    float Ab[16];              // Abar (row-major 4x4)
    float Bb[4];               // Bbar
    float Pk[NROUND][16];      // Abar^(L_CH * 2^r)
};

// Static scratch (no allocs). B <= 8 supported.
__device__ float4 g_start[8 * NCHUNK * D_DIM];  // start-states, [b][j][d]

// One recurrence step: x = Ab*x + Bb*hv
#define RSTEP(hv)                                                              \
    {                                                                          \
        float y0 = fmaf(c.Ab[0],  x0, fmaf(c.Ab[1],  x1,                       \
                   fmaf(c.Ab[2],  x2, fmaf(c.Ab[3],  x3, c.Bb[0] * (hv)))));   \
        float y1 = fmaf(c.Ab[4],  x0, fmaf(c.Ab[5],  x1,                       \
                   fmaf(c.Ab[6],  x2, fmaf(c.Ab[7],  x3, c.Bb[1] * (hv)))));   \
        float y2 = fmaf(c.Ab[8],  x0, fmaf(c.Ab[9],  x1,                       \
                   fmaf(c.Ab[10], x2, fmaf(c.Ab[11], x3, c.Bb[2] * (hv)))));   \
        float y3 = fmaf(c.Ab[12], x0, fmaf(c.Ab[13], x1,                       \
                   fmaf(c.Ab[14], x2, fmaf(c.Ab[15], x3, c.Bb[3] * (hv)))));   \
        x0 = y0; x1 = y1; x2 = y2; x3 = y3;                                    \
    }

// v = M*p + v  (4x4 matvec-accumulate on float4)
__device__ __forceinline__ float4 mvacc(const float* M, float4 p, float4 v) {
    float4 r;
    r.x = fmaf(M[0],  p.x, fmaf(M[1],  p.y, fmaf(M[2],  p.z, fmaf(M[3],  p.w, v.x))));
    r.y = fmaf(M[4],  p.x, fmaf(M[5],  p.y, fmaf(M[6],  p.z, fmaf(M[7],  p.w, v.y))));
    r.z = fmaf(M[8],  p.x, fmaf(M[9],  p.y, fmaf(M[10], p.z, fmaf(M[11], p.w, v.z))));
    r.w = fmaf(M[12], p.x, fmaf(M[13], p.y, fmaf(M[14], p.z, fmaf(M[15], p.w, v.w))));
    return r;
}

#define SSTR 5   // slab row stride in floats (padding vs bank conflicts)

// ---- Kernel A: per (b, 4-d group): local chunk recurrences + in-block scan ----
// threads: tid = j*DG + dd (j = chunk 0..127, dd = 0..3)
__global__ __launch_bounds__(ATHR)
void hippo_scan(const float* __restrict__ h, HippoConsts c) {
    __shared__ float  sh[T_LEN * SSTR];   // slab: sh[t*5 + dd]
    __shared__ float4 s[ATHR];            // scan workspace

    const int tid = threadIdx.x;
    const int g   = blockIdx.x;           // d-group (0..63)
    const int b   = blockIdx.y;
    const int d0  = g * DG;

    // stage slab: thread loads rows 2*tid, 2*tid+1 (one float4 each)
    {
        const float* hb = h + (size_t)b * T_LEN * D_DIM + d0;
        const int r0 = tid * 2;
        float4 a0 = __ldg((const float4*)(hb + (size_t)r0 * D_DIM));
        float4 a1 = __ldg((const float4*)(hb + (size_t)(r0 + 1) * D_DIM));
        float* p0 = sh + r0 * SSTR;
        p0[0] = a0.x; p0[1] = a0.y; p0[2] = a0.z; p0[3] = a0.w;
        float* p1 = sh + (r0 + 1) * SSTR;
        p1[0] = a1.x; p1[1] = a1.y; p1[2] = a1.z; p1[3] = a1.w;
    }
    __syncthreads();

    const int j  = tid >> 2;          // chunk
    const int dd = tid & 3;           // d within group
    const float* col = sh + (size_t)(j * L_CH) * SSTR + dd;

    // chunk-local recurrence (zero init)
    float x0 = 0.f, x1 = 0.f, x2 = 0.f, x3 = 0.f;
    #pragma unroll
    for (int t = 0; t < L_CH; t++) {
        float hv = col[t * SSTR];
        RSTEP(hv);
    }
    float4 v = make_float4(x0, x1, x2, x3);
    s[tid] = v;
    __syncthreads();

    // Kogge-Stone affine scan over 128 chunks (per dd independently)
    #pragma unroll
    for (int r = 0; r < NROUND; r++) {
        const int off = 1 << r;
        float4 prev = make_float4(0.f, 0.f, 0.f, 0.f);
        const bool pred = (j >= off);
        if (pred) prev = s[tid - off * DG];
        __syncthreads();
        if (pred) v = mvacc(c.Pk[r], prev, v);   // v += P^(2^r) * prev
        s[tid] = v;
        __syncthreads();
    }

    // exclusive prefix -> start states, [b][j][d] layout (coalesced reads in K2)
    float4 st = make_float4(0.f, 0.f, 0.f, 0.f);
    if (j > 0) st = s[tid - DG];
    g_start[((size_t)b * NCHUNK + j) * D_DIM + d0 + dd] = st;
}

// ---- Kernel B: replay each chunk from its start state, writing all outputs ----
__global__ __launch_bounds__(D_DIM)
void hippo_k2(const float* __restrict__ h, float* __restrict__ out, HippoConsts c) {
    __shared__ float sh[L_CH * D_DIM];   // 8KB chunk stage
    const int tid = threadIdx.x;
    const int j = blockIdx.x;
    const int b = blockIdx.y;

    // issue start-state + h loads together (independent)
    float4 xs = g_start[((size_t)b * NCHUNK + j) * D_DIM + tid];
    const float4* src = (const float4*)(h + ((size_t)(b * T_LEN + j * L_CH)) * D_DIM);
    float4 v0 = __ldg(src + tid);
    float4 v1 = __ldg(src + D_DIM + tid);
    ((float4*)sh)[tid] = v0;
    ((float4*)sh)[D_DIM + tid] = v1;
    __syncthreads();

    float x0 = xs.x, x1 = xs.y, x2 = xs.z, x3 = xs.w;
    float* op = out + ((size_t)(b * T_LEN + j * L_CH)) * K_CH * D_DIM + tid;

    #pragma unroll
    for (int t = 0; t < L_CH; t++) {
        float hv = sh[t * D_DIM + tid];
        RSTEP(hv);
        op[0]         = x0;
        op[D_DIM]     = x1;
        op[2 * D_DIM] = x2;
        op[3 * D_DIM] = x3;
        op += (size_t)K_CH * D_DIM;
    }
}

// ---------------- host-side constant construction (double precision) ----------------

static void inv4x4(const double Min[4][4], double Mout[4][4]) {
    double a[4][8];
    for (int i = 0; i < 4; i++)
        for (int jj = 0; jj < 8; jj++)
            a[i][jj] = (jj < 4) ? Min[i][jj] : (jj - 4 == i ? 1.0 : 0.0);
    for (int col = 0; col < 4; col++) {
        int p = col;
        for (int rr = col + 1; rr < 4; rr++)
            if (fabs(a[rr][col]) > fabs(a[p][col])) p = rr;
        if (p != col)
            for (int jj = 0; jj < 8; jj++) { double t = a[col][jj]; a[col][jj] = a[p][jj]; a[p][jj] = t; }
        double piv = a[col][col];
        for (int jj = 0; jj < 8; jj++) a[col][jj] /= piv;
        for (int rr = 0; rr < 4; rr++) {
            if (rr == col) continue;
            double f = a[rr][col];
            for (int jj = 0; jj < 8; jj++) a[rr][jj] -= f * a[col][jj];
        }
    }
    for (int i = 0; i < 4; i++)
        for (int jj = 0; jj < 4; jj++)
            Mout[i][jj] = a[i][jj + 4];
}

static void matmul4(const double A[4][4], const double B[4][4], double C[4][4]) {
    for (int i = 0; i < 4; i++)
        for (int jj = 0; jj < 4; jj++) {
            double s = 0.0;
            for (int k = 0; k < 4; k++) s += A[i][k] * B[k][jj];
            C[i][jj] = s;
        }
}

extern "C" void kernel_launch(void* const* d_in, const int* in_sizes, int n_in,
                              void* d_out, int out_size) {
    const float* h;
    int sz0 = in_sizes[0], sz1 = in_sizes[1];
    if (sz0 > sz1) h = (const float*)d_in[0];
    else           h = (const float*)d_in[1];
    int hsz = (sz0 > sz1) ? sz0 : sz1;
    int B = hsz / (T_LEN * D_DIM);

    // --- HiPPO-LegT constants (matches reference _make_hippo_legt + bilinear) ---
    const double theta = 200.0;
    const double dt = 1.0 / theta;
    double A[4][4], Bv[4], Pn[4];
    for (int i = 0; i < 4; i++) Pn[i] = sqrt(2.0 * i + 1.0);
    for (int i = 0; i < 4; i++) {
        Bv[i] = Pn[i];
        for (int jj = 0; jj < 4; jj++) {
            double sg = 1.0;
            if (jj > i && ((jj - i) & 1)) sg = -1.0;   // (-1)^(j-i) upper triangle
            A[i][jj] = -Pn[i] * Pn[jj] * sg;
        }
    }
    double ImA[4][4], IpA[4][4], Inv[4][4], Abar[4][4];
    for (int i = 0; i < 4; i++)
        for (int jj = 0; jj < 4; jj++) {
            double eye = (i == jj) ? 1.0 : 0.0;
            ImA[i][jj] = eye - 0.5 * dt * A[i][jj];
            IpA[i][jj] = eye + 0.5 * dt * A[i][jj];
        }
    inv4x4(ImA, Inv);
    matmul4(Inv, IpA, Abar);
    double Bbar[4];
    for (int i = 0; i < 4; i++) {
        double sacc = 0.0;
        for (int jj = 0; jj < 4; jj++) sacc += Inv[i][jj] * Bv[jj] * dt;
        Bbar[i] = sacc;
    }

    // Pk[r] = Abar^(L_CH * 2^r)
    double Pw[NROUND][4][4], Tmp[4][4], Cur[4][4];
    for (int i = 0; i < 4; i++)
        for (int jj = 0; jj < 4; jj++) Cur[i][jj] = (i == jj) ? 1.0 : 0.0;
    for (int m = 0; m < L_CH; m++) {
        matmul4(Cur, Abar, Tmp);
        for (int i = 0; i < 4; i++)
            for (int jj = 0; jj < 4; jj++) Cur[i][jj] = Tmp[i][jj];
    }
    for (int i = 0; i < 4; i++)
        for (int jj = 0; jj < 4; jj++) Pw[0][i][jj] = Cur[i][jj];
    for (int r = 1; r < NROUND; r++) {
        matmul4(Pw[r - 1], Pw[r - 1], Tmp);
        for (int i = 0; i < 4; i++)
            for (int jj = 0; jj < 4; jj++) Pw[r][i][jj] = Tmp[i][jj];
    }

    HippoConsts c;
    for (int i = 0; i < 4; i++) {
        c.Bb[i] = (float)Bbar[i];
        for (int jj = 0; jj < 4; jj++)
            c.Ab[i * 4 + jj] = (float)Abar[i][jj];
    }
    for (int r = 0; r < NROUND; r++)
        for (int i = 0; i < 16; i++)
            c.Pk[r][i] = (float)Pw[r][i / 4][i % 4];

    dim3 gridA(D_DIM / DG, B);      // 64 x B = 128 blocks
    dim3 gridB(NCHUNK, B);          // 128 x B = 256 blocks
    hippo_scan<<<gridA, ATHR>>>(h, c);
    hippo_k2<<<gridB, D_DIM>>>(h, (float*)d_out, c);
}